// round 1
// baseline (speedup 1.0000x reference)
#include <cuda_runtime.h>

// GATLayer: B=8, N=1024, INP=7, D=32, H=4
// Key identity: softmax_j(s_i + s_j + ba) == softmax_j(s_j)  (s_i, ba constant in j)
// => att is independent of i => out[b,i,:] is constant over i.

#define BB 8
#define NN 1024
#define DD 32
#define HH 4

// scratch (no allocations allowed)
__device__ float4 g_fx4[BB * NN * 8];   // fx [8192][32] viewed as float4[8192][8]
__device__ float4 g_s4[BB * NN];        // s_j [8192][4]
__device__ __align__(16) float g_o[BB * DD];  // per-batch output row [8][32]

static __device__ __forceinline__ float lrelu(float t) {
    // leaky_relu(t, 0.2) == max(t, 0.2*t)
    return fmaxf(t, 0.2f * t);
}

// ---------------------------------------------------------------------------
// Kernel 1: message MLP + s_j. Two threads per node (split layer-2 j-range),
// weights staged in shared (W2 transposed for LDS.128 on the K dot).
// grid: 128 blocks x 128 threads (64 nodes/block)
// ---------------------------------------------------------------------------
__global__ __launch_bounds__(128) void k_mlp(
    const float* __restrict__ x,
    const float* __restrict__ W1, const float* __restrict__ b1,
    const float* __restrict__ W2, const float* __restrict__ b2,
    const float* __restrict__ W3, const float* __restrict__ b3,
    const float* __restrict__ Wa)
{
    __shared__ float sW1[7 * 64];
    __shared__ float sb1[64];
    __shared__ float sW2t[64 * 64];   // [j][k]
    __shared__ float sb2[64];
    __shared__ float sW3[64 * 32];    // [j][d]
    __shared__ float sb3[32];
    __shared__ float sWaj[32 * 4];    // Wa rows 32..63 ([d][h])

    const int t = threadIdx.x;
    for (int i = t; i < 448; i += 128) sW1[i] = W1[i];
    for (int i = t; i < 4096; i += 128) { int k = i >> 6, j = i & 63; sW2t[j * 64 + k] = W2[i]; }
    for (int i = t; i < 2048; i += 128) sW3[i] = W3[i];
    if (t < 128) sWaj[t] = Wa[128 + t];
    if (t < 64) sb1[t] = b1[t];
    if (t < 64) sb2[t] = b2[t];
    if (t < 32) sb3[t] = b3[t];
    __syncthreads();

    const int node = blockIdx.x * 64 + (t >> 1);
    const int half = t & 1;

    float xv[7];
#pragma unroll
    for (int k = 0; k < 7; k++) xv[k] = x[node * 7 + k];

    // layer 1 (full, both threads of the pair)
    float h1[64];
#pragma unroll
    for (int j = 0; j < 64; j++) h1[j] = sb1[j];
#pragma unroll
    for (int k = 0; k < 7; k++) {
        const float xk = xv[k];
#pragma unroll
        for (int j = 0; j < 64; j++) h1[j] += xk * sW1[k * 64 + j];
    }
#pragma unroll
    for (int j = 0; j < 64; j++) h1[j] = lrelu(h1[j]);

    // layer 2 + layer 3 partial: each thread handles 32 of the 64 hidden j's
    float fx[32];
#pragma unroll
    for (int d = 0; d < 32; d++) fx[d] = half ? 0.0f : sb3[d];

    const int j0 = half * 32;
#pragma unroll 2
    for (int jj = 0; jj < 32; jj++) {
        const int j = j0 + jj;
        float a = sb2[j];
        const float4* w2r = (const float4*)(sW2t + (j << 6));
#pragma unroll
        for (int k4 = 0; k4 < 16; k4++) {
            const float4 w = w2r[k4];
            a += h1[k4 * 4 + 0] * w.x;
            a += h1[k4 * 4 + 1] * w.y;
            a += h1[k4 * 4 + 2] * w.z;
            a += h1[k4 * 4 + 3] * w.w;
        }
        a = lrelu(a);
        const float4* w3r = (const float4*)(sW3 + (j << 5));
#pragma unroll
        for (int d4 = 0; d4 < 8; d4++) {
            const float4 w = w3r[d4];
            fx[d4 * 4 + 0] += a * w.x;
            fx[d4 * 4 + 1] += a * w.y;
            fx[d4 * 4 + 2] += a * w.z;
            fx[d4 * 4 + 3] += a * w.w;
        }
    }

    // combine the pair's partial fx
#pragma unroll
    for (int d = 0; d < 32; d++) fx[d] += __shfl_xor_sync(0xffffffffu, fx[d], 1);

    if (half == 0) {
        float4* o = &g_fx4[node * 8];
#pragma unroll
        for (int q = 0; q < 8; q++)
            o[q] = make_float4(fx[q * 4], fx[q * 4 + 1], fx[q * 4 + 2], fx[q * 4 + 3]);
    } else {
        // s_j = fx @ Wa[D:]   (only the j-contribution is needed)
        float s0 = 0.f, s1 = 0.f, s2 = 0.f, s3 = 0.f;
#pragma unroll
        for (int d = 0; d < 32; d++) {
            const float f = fx[d];
            const float4 w = *(const float4*)(sWaj + d * 4);
            s0 += f * w.x; s1 += f * w.y; s2 += f * w.z; s3 += f * w.w;
        }
        g_s4[node] = make_float4(s0, s1, s2, s3);
    }
}

// ---------------------------------------------------------------------------
// Kernel 2: per-batch softmax over j, weighted aggregation m[h][d], final
// projection o = m.flat @ Ws + bs. One block per batch.
// grid: 8 blocks x 256 threads
// ---------------------------------------------------------------------------
__global__ __launch_bounds__(256) void k_att(
    const float* __restrict__ Ws, const float* __restrict__ bs)
{
    const int b = blockIdx.x;
    const int t = threadIdx.x;

    __shared__ float ps[4 * 1024];     // exp(s - max), [h][j]
    __shared__ float red[4][256];
    __shared__ float mxs[4];
    __shared__ float sums[4];
    __shared__ float sm[128];          // m[h][d] normalized, head-major flat

    float sv[4][4];
    float lmax[4] = { -1e30f, -1e30f, -1e30f, -1e30f };
#pragma unroll
    for (int jj = 0; jj < 4; jj++) {
        const float4 v = g_s4[b * 1024 + t + jj * 256];
        sv[jj][0] = v.x; sv[jj][1] = v.y; sv[jj][2] = v.z; sv[jj][3] = v.w;
        lmax[0] = fmaxf(lmax[0], v.x);
        lmax[1] = fmaxf(lmax[1], v.y);
        lmax[2] = fmaxf(lmax[2], v.z);
        lmax[3] = fmaxf(lmax[3], v.w);
    }
#pragma unroll
    for (int h = 0; h < 4; h++) red[h][t] = lmax[h];
    __syncthreads();
    for (int s = 128; s > 0; s >>= 1) {
        if (t < s) {
#pragma unroll
            for (int h = 0; h < 4; h++) red[h][t] = fmaxf(red[h][t], red[h][t + s]);
        }
        __syncthreads();
    }
    if (t < 4) mxs[t] = red[t][0];
    __syncthreads();

    float lsum[4] = { 0.f, 0.f, 0.f, 0.f };
#pragma unroll
    for (int jj = 0; jj < 4; jj++) {
        const int j = t + jj * 256;
#pragma unroll
        for (int h = 0; h < 4; h++) {
            const float e = __expf(sv[jj][h] - mxs[h]);
            ps[h * 1024 + j] = e;
            lsum[h] += e;
        }
    }
#pragma unroll
    for (int h = 0; h < 4; h++) red[h][t] = lsum[h];
    __syncthreads();
    for (int s = 128; s > 0; s >>= 1) {
        if (t < s) {
#pragma unroll
            for (int h = 0; h < 4; h++) red[h][t] += red[h][t + s];
        }
        __syncthreads();
    }
    if (t < 4) sums[t] = red[t][0];
    __syncthreads();

    // m[h][d] = (sum_j e[j,h] * fx[b,j,d]) / sum_e[h]
    if (t < 128) {
        const int h = t >> 5, d = t & 31;
        const float* fxb = ((const float*)g_fx4) + b * NN * DD + d;
        const float* pr = ps + h * 1024;
        float acc = 0.f;
#pragma unroll 8
        for (int j = 0; j < 1024; j++) acc += pr[j] * __ldg(fxb + j * 32);
        sm[t] = acc / sums[h];
    }
    __syncthreads();

    // o[d] = bs[d] + sum_k sm[k] * Ws[k][d]
    if (t < 32) {
        float o = bs[t];
#pragma unroll
        for (int k = 0; k < 128; k++) o += sm[k] * Ws[k * 32 + t];
        g_o[b * 32 + t] = o;
    }
}

// ---------------------------------------------------------------------------
// Kernel 3: broadcast per-batch row to full [B,N,D] output (float4 stores).
// grid: 256 blocks x 256 threads = 65536 float4 = 262144 floats
// ---------------------------------------------------------------------------
__global__ __launch_bounds__(256) void k_bcast(float4* __restrict__ out)
{
    const int g = blockIdx.x * 256 + threadIdx.x; // float4 index
    const int b = g >> 13;                        // 8192 float4 per batch
    const int d4 = g & 7;                         // 8 float4 per row
    out[g] = *(const float4*)(g_o + b * 32 + d4 * 4);
}

extern "C" void kernel_launch(void* const* d_in, const int* in_sizes, int n_in,
                              void* d_out, int out_size)
{
    const float* x  = (const float*)d_in[0];
    const float* W1 = (const float*)d_in[1];
    const float* b1 = (const float*)d_in[2];
    const float* W2 = (const float*)d_in[3];
    const float* b2 = (const float*)d_in[4];
    const float* W3 = (const float*)d_in[5];
    const float* b3 = (const float*)d_in[6];
    const float* Wa = (const float*)d_in[7];
    // d_in[8] = ba: cancels inside the softmax, unused
    const float* Ws = (const float*)d_in[9];
    const float* bs = (const float*)d_in[10];

    k_mlp<<<128, 128>>>(x, W1, b1, W2, b2, W3, b3, Wa);
    k_att<<<8, 256>>>(Ws, bs);
    k_bcast<<<256, 256>>>((float4*)d_out);
}

// round 4
// speedup vs baseline: 2.1229x; 2.1229x over previous
#include <cuda_runtime.h>

// GATLayer: B=8, N=1024, INP=7, D=32, H=4
// Identity: softmax_j(s_i + s_j + ba) == softmax_j(s_j) (s_i, ba constant in j)
// => attention weights independent of i => output row constant per batch.

#define BB 8
#define NN 1024
#define DD 32
#define HH 4

__device__ float4 g_fx4[BB * NN * 8];        // fx [8192][32] as float4[8192][8]
__device__ float4 g_s4[BB * NN];             // s_j [8192][4]
__device__ __align__(16) float g_o[BB * DD]; // per-batch output row [8][32]

static __device__ __forceinline__ float lrelu(float t) {
    return fmaxf(t, 0.2f * t);
}

// ---------------------------------------------------------------------------
// Kernel 1: message MLP + s_j.
// 128 blocks x 256 threads; 4 threads per node (quarter q = t&3 owns 16 of the
// 64 layer-2 units). Layer-1 (cheap) duplicated per quarter; layers 2-3 split.
// All dots are accumulator-parallel (no long FFMA chains).
// ---------------------------------------------------------------------------
__global__ __launch_bounds__(256) void k_mlp(
    const float* __restrict__ x,
    const float* __restrict__ W1, const float* __restrict__ b1,
    const float* __restrict__ W2, const float* __restrict__ b2,
    const float* __restrict__ W3, const float* __restrict__ b3,
    const float* __restrict__ Wa)
{
    __shared__ float sW1[7 * 64];
    __shared__ float sb1[64];
    __shared__ float sW2[64 * 64];     // natural [k][j]
    __shared__ float sb2[64];
    __shared__ float sW3s[2080];       // skewed: (j,d) at j*32 + (j>>4)*8 + d
    __shared__ float sb3[32];
    __shared__ float sWaj[32 * 4];     // Wa rows 32..63, [d][h]

    const int t = threadIdx.x;
    for (int i = t; i < 448; i += 256) sW1[i] = W1[i];
    for (int i = t; i < 4096; i += 256) sW2[i] = W2[i];
    for (int i = t; i < 2048; i += 256) {
        const int j = i >> 5, d = i & 31;
        sW3s[j * 32 + ((j >> 4) << 3) + d] = W3[i];
    }
    if (t < 128) sWaj[t] = Wa[128 + t];
    if (t < 64) sb1[t] = b1[t];
    else if (t < 128) sb2[t - 64] = b2[t - 64];
    else if (t < 160) sb3[t - 128] = b3[t - 128];
    __syncthreads();

    const int node = blockIdx.x * 64 + (t >> 2);
    const int q = t & 3;
    const int j0 = q * 16;

    float xv[7];
#pragma unroll
    for (int k = 0; k < 7; k++) xv[k] = x[node * 7 + k];

    // ---- layer 1: full 64 units (accumulator-parallel over j) ----
    float h1[64];
#pragma unroll
    for (int j4 = 0; j4 < 16; j4++) {
        const float4 b = *(const float4*)(sb1 + j4 * 4);
        h1[j4 * 4 + 0] = b.x; h1[j4 * 4 + 1] = b.y;
        h1[j4 * 4 + 2] = b.z; h1[j4 * 4 + 3] = b.w;
    }
#pragma unroll
    for (int k = 0; k < 7; k++) {
        const float xk = xv[k];
#pragma unroll
        for (int j4 = 0; j4 < 16; j4++) {
            const float4 w = *(const float4*)(sW1 + k * 64 + j4 * 4);
            h1[j4 * 4 + 0] += xk * w.x;
            h1[j4 * 4 + 1] += xk * w.y;
            h1[j4 * 4 + 2] += xk * w.z;
            h1[j4 * 4 + 3] += xk * w.w;
        }
    }
#pragma unroll
    for (int j = 0; j < 64; j++) h1[j] = lrelu(h1[j]);

    // ---- layer 2: 16 units (q's slice), k-outer so a16[] are parallel accs.
    // Column order rotated per-quarter so the 4 lanes of a quad hit distinct
    // shared banks ({0,20,8,28} mod 32 instead of {0,16,0,16}).
    int colof[4];
#pragma unroll
    for (int cc = 0; cc < 4; cc++) colof[cc] = j0 + (((cc + q) & 3) << 2);

    float a16[16];
#pragma unroll
    for (int cc = 0; cc < 4; cc++) {
        const float4 b = *(const float4*)(sb2 + colof[cc]);
        a16[cc * 4 + 0] = b.x; a16[cc * 4 + 1] = b.y;
        a16[cc * 4 + 2] = b.z; a16[cc * 4 + 3] = b.w;
    }
#pragma unroll
    for (int k = 0; k < 64; k++) {
        const float hk = h1[k];
        const float* row = sW2 + k * 64;
#pragma unroll
        for (int cc = 0; cc < 4; cc++) {
            const float4 w = *(const float4*)(row + colof[cc]);
            a16[cc * 4 + 0] += hk * w.x;
            a16[cc * 4 + 1] += hk * w.y;
            a16[cc * 4 + 2] += hk * w.z;
            a16[cc * 4 + 3] += hk * w.w;
        }
    }

    // ---- layer 3: partial fx over q's 16 units; W3 tile is bank-skewed ----
    float fx[32];
    if (q == 0) {
#pragma unroll
        for (int d4 = 0; d4 < 8; d4++) {
            const float4 b = *(const float4*)(sb3 + d4 * 4);
            fx[d4 * 4 + 0] = b.x; fx[d4 * 4 + 1] = b.y;
            fx[d4 * 4 + 2] = b.z; fx[d4 * 4 + 3] = b.w;
        }
    } else {
#pragma unroll
        for (int d = 0; d < 32; d++) fx[d] = 0.0f;
    }
#pragma unroll
    for (int cc = 0; cc < 4; cc++) {
#pragma unroll
        for (int c = 0; c < 4; c++) {
            const int j = colof[cc] + c;         // in [j0, j0+16)
            const float aj = lrelu(a16[cc * 4 + c]);
            const float* w3row = sW3s + j * 32 + (q << 3); // j>>4 == q
#pragma unroll
            for (int d4 = 0; d4 < 8; d4++) {
                const float4 w = *(const float4*)(w3row + d4 * 4);
                fx[d4 * 4 + 0] += aj * w.x;
                fx[d4 * 4 + 1] += aj * w.y;
                fx[d4 * 4 + 2] += aj * w.z;
                fx[d4 * 4 + 3] += aj * w.w;
            }
        }
    }

    // combine partial fx across the quad
#pragma unroll
    for (int d = 0; d < 32; d++) {
        fx[d] += __shfl_xor_sync(0xffffffffu, fx[d], 1);
        fx[d] += __shfl_xor_sync(0xffffffffu, fx[d], 2);
    }

    if (q == 0) {
        float4* o = &g_fx4[node * 8];
#pragma unroll
        for (int c4 = 0; c4 < 8; c4++)
            o[c4] = make_float4(fx[c4 * 4], fx[c4 * 4 + 1], fx[c4 * 4 + 2], fx[c4 * 4 + 3]);
    } else if (q == 1) {
        float s0 = 0.f, s1 = 0.f, s2 = 0.f, s3 = 0.f;
#pragma unroll
        for (int d = 0; d < 32; d++) {
            const float f = fx[d];
            const float4 w = *(const float4*)(sWaj + d * 4);
            s0 += f * w.x; s1 += f * w.y; s2 += f * w.z; s3 += f * w.w;
        }
        g_s4[node] = make_float4(s0, s1, s2, s3);
    }
}

// ---------------------------------------------------------------------------
// Kernel 2: per-batch softmax over j, aggregation m[h][d] (fx tiled through
// shared), projection. 8 blocks x 256 threads.
// ---------------------------------------------------------------------------
__global__ __launch_bounds__(256) void k_att(
    const float* __restrict__ Ws, const float* __restrict__ bs)
{
    const int b = blockIdx.x;
    const int t = threadIdx.x;
    const int w = t >> 5, lane = t & 31;

    __shared__ float ps[4 * 1024];   // exp(s - max), [h][j]
    __shared__ float4 sfx4[256 * 8]; // 256-row fx tile (32 KB)
    __shared__ float red[4 * 8];
    __shared__ float part[256];
    __shared__ float sm[128];
    __shared__ float pr2[128];

    // ---- load s, per-head max ----
    float sv[4][4];
    float lmax[4] = { -1e30f, -1e30f, -1e30f, -1e30f };
#pragma unroll
    for (int jj = 0; jj < 4; jj++) {
        const float4 v = g_s4[b * 1024 + jj * 256 + t];
        sv[jj][0] = v.x; sv[jj][1] = v.y; sv[jj][2] = v.z; sv[jj][3] = v.w;
        lmax[0] = fmaxf(lmax[0], v.x); lmax[1] = fmaxf(lmax[1], v.y);
        lmax[2] = fmaxf(lmax[2], v.z); lmax[3] = fmaxf(lmax[3], v.w);
    }
#pragma unroll
    for (int o = 16; o > 0; o >>= 1)
#pragma unroll
        for (int h = 0; h < 4; h++)
            lmax[h] = fmaxf(lmax[h], __shfl_xor_sync(0xffffffffu, lmax[h], o));
    if (lane == 0)
#pragma unroll
        for (int h = 0; h < 4; h++) red[h * 8 + w] = lmax[h];
    __syncthreads();
    float mx[4];
#pragma unroll
    for (int h = 0; h < 4; h++) {
        float m = red[h * 8];
#pragma unroll
        for (int ww = 1; ww < 8; ww++) m = fmaxf(m, red[h * 8 + ww]);
        mx[h] = m;
    }
    __syncthreads();

    // ---- exp + per-head sum ----
    float lsum[4] = { 0.f, 0.f, 0.f, 0.f };
#pragma unroll
    for (int jj = 0; jj < 4; jj++) {
        const int j = jj * 256 + t;
#pragma unroll
        for (int h = 0; h < 4; h++) {
            const float e = __expf(sv[jj][h] - mx[h]);
            ps[h * 1024 + j] = e;
            lsum[h] += e;
        }
    }
#pragma unroll
    for (int o = 16; o > 0; o >>= 1)
#pragma unroll
        for (int h = 0; h < 4; h++)
            lsum[h] += __shfl_xor_sync(0xffffffffu, lsum[h], o);
    if (lane == 0)
#pragma unroll
        for (int h = 0; h < 4; h++) red[h * 8 + w] = lsum[h];
    __syncthreads();
    float sums[4];
#pragma unroll
    for (int h = 0; h < 4; h++) {
        float s = red[h * 8];
#pragma unroll
        for (int ww = 1; ww < 8; ww++) s += red[h * 8 + ww];
        sums[h] = s;
    }

    // ---- aggregation: m[h][d] = sum_j p[h][j]*fx[j][d], fx tiled via smem.
    // 2 threads per (h,d): o = t&127, half = t>>7 handles half the tile rows.
    const int o = t & 127, half = t >> 7;
    const int h = o >> 5, d = o & 31;
    float a0 = 0.f, a1 = 0.f, a2 = 0.f, a3 = 0.f;
#pragma unroll 1
    for (int tile = 0; tile < 4; tile++) {
        __syncthreads();                               // protect previous tile
        const float4* src = g_fx4 + (b * 1024 + tile * 256) * 8;
        for (int i = t; i < 2048; i += 256) sfx4[i] = src[i];
        __syncthreads();
        const float* pr  = ps + h * 1024 + tile * 256 + half * 128;
        const float* fxp = (const float*)sfx4 + half * 128 * 32 + d;
#pragma unroll 8
        for (int jj = 0; jj < 128; jj += 4) {
            a0 += pr[jj + 0] * fxp[(jj + 0) * 32];
            a1 += pr[jj + 1] * fxp[(jj + 1) * 32];
            a2 += pr[jj + 2] * fxp[(jj + 2) * 32];
            a3 += pr[jj + 3] * fxp[(jj + 3) * 32];
        }
    }
    part[t] = (a0 + a1) + (a2 + a3);
    __syncthreads();
    if (t < 128) sm[t] = (part[t] + part[t + 128]) / sums[h];
    __syncthreads();

    // ---- projection: o[d] = bs[d] + sum_k sm[k]*Ws[k][d] (128 thr, 4-way k split)
    if (t < 128) {
        const int kg = t >> 5, dd = t & 31;
        float a = 0.f;
#pragma unroll
        for (int kk = 0; kk < 32; kk++) {
            const int k = kg * 32 + kk;
            a += sm[k] * Ws[k * 32 + dd];
        }
        pr2[t] = a;
    }
    __syncthreads();
    if (t < 32)
        g_o[b * 32 + t] = bs[t] + ((pr2[t] + pr2[t + 32]) + (pr2[t + 64] + pr2[t + 96]));
}

// ---------------------------------------------------------------------------
// Kernel 3: broadcast per-batch rows to the full [B,N,D] output.
// ---------------------------------------------------------------------------
__global__ __launch_bounds__(256) void k_bcast(float4* __restrict__ out)
{
    const int g = blockIdx.x * 256 + threadIdx.x; // float4 index
    const int b = g >> 13;                        // 8192 float4 per batch
    const int d4 = g & 7;
    out[g] = *(const float4*)(g_o + b * 32 + d4 * 4);
}

extern "C" void kernel_launch(void* const* d_in, const int* in_sizes, int n_in,
                              void* d_out, int out_size)
{
    const float* x  = (const float*)d_in[0];
    const float* W1 = (const float*)d_in[1];
    const float* b1 = (const float*)d_in[2];
    const float* W2 = (const float*)d_in[3];
    const float* b2 = (const float*)d_in[4];
    const float* W3 = (const float*)d_in[5];
    const float* b3 = (const float*)d_in[6];
    const float* Wa = (const float*)d_in[7];
    // d_in[8] = ba: cancels in the softmax
    const float* Ws = (const float*)d_in[9];
    const float* bs = (const float*)d_in[10];

    k_mlp<<<128, 256>>>(x, W1, b1, W2, b2, W3, b3, Wa);
    k_att<<<8, 256>>>(Ws, bs);
    k_bcast<<<256, 256>>>((float4*)d_out);
}